// round 17
// baseline (speedup 1.0000x reference)
#include <cuda_runtime.h>
#include <cuda_fp16.h>
#include <math.h>
#include <stdint.h>

// Problem dims (fixed per reference)
#define BATCH   1024
#define IN_DIM  1024
#define HID     4096
#define KX      (IN_DIM + HID)   // 5120
#define G4      (4 * HID)        // 16384
#define OUT_DIM 4096

// ---------------- scratch (no cudaMalloc allowed) ----------------
// Referenced ONLY inside device code (host-side use would get the host shadow).
__device__ __align__(16) __half g_xh[BATCH * KX];
__device__ __align__(16) __half g_wh[(size_t)G4 * KX];     // gate-interleaved rows: r = j*4+gate
__device__ __align__(16) __half g_wouth[(size_t)OUT_DIM * HID];
__device__ __align__(16) __half g_hth[BATCH * HID];
__device__ float g_logits[(size_t)BATCH * OUT_DIM];

// ---------------- PTX helpers ----------------
__device__ __forceinline__ uint32_t smem_u32(const void* p) {
    uint32_t a;
    asm("{ .reg .u64 t; cvta.to.shared.u64 t, %1; cvt.u32.u64 %0, t; }" : "=r"(a) : "l"(p));
    return a;
}
__device__ __forceinline__ void cp16(uint32_t s, const void* g) {
    asm volatile("cp.async.cg.shared.global [%0], [%1], 16;" :: "r"(s), "l"(g) : "memory");
}
__device__ __forceinline__ void cp_commit() {
    asm volatile("cp.async.commit_group;" ::: "memory");
}
__device__ __forceinline__ void cp_wait0() {
    asm volatile("cp.async.wait_group 0;" ::: "memory");
}
__device__ __forceinline__ void ldsm4(uint32_t* r, uint32_t addr) {
    asm volatile("ldmatrix.sync.aligned.m8n8.x4.shared.b16 {%0,%1,%2,%3}, [%4];"
                 : "=r"(r[0]), "=r"(r[1]), "=r"(r[2]), "=r"(r[3]) : "r"(addr));
}
__device__ __forceinline__ void mma16816(float* d, const uint32_t* a, uint32_t b0, uint32_t b1) {
    asm volatile("mma.sync.aligned.m16n8k16.row.col.f32.f16.f16.f32 "
                 "{%0,%1,%2,%3}, {%4,%5,%6,%7}, {%8,%9}, {%0,%1,%2,%3};"
                 : "+f"(d[0]), "+f"(d[1]), "+f"(d[2]), "+f"(d[3])
                 : "r"(a[0]), "r"(a[1]), "r"(a[2]), "r"(a[3]), "r"(b0), "r"(b1));
}

// ---------------- fp32 -> fp16 converters (vectorized) ----------------
__device__ __forceinline__ void cvt4_store(float4 v, __half* dst) {
    __half2 h0 = __floats2half2_rn(v.x, v.y);
    __half2 h1 = __floats2half2_rn(v.z, v.w);
    uint2 u;
    u.x = *(uint32_t*)&h0;
    u.y = *(uint32_t*)&h1;
    *(uint2*)dst = u;
}

__global__ void convert_x_kernel(const float* __restrict__ i_, const float* __restrict__ h_) {
    const int b = blockIdx.x;
    for (int k4 = threadIdx.x; k4 < KX / 4; k4 += blockDim.x) {
        int k = k4 * 4;
        float4 v = (k < IN_DIM) ? *(const float4*)(i_ + (size_t)b * IN_DIM + k)
                                : *(const float4*)(h_ + (size_t)b * HID + (k - IN_DIM));
        cvt4_store(v, &g_xh[(size_t)b * KX + k]);
    }
}

// Gate-interleaved W: dst row (j*4 + gate) <- gate-weight row j.
// blockIdx.x = source row id within one gate stack (0..HID-1), 4 gates handled per block.
__global__ void convert_w_kernel(const float* __restrict__ Wf, const float* __restrict__ Wi,
                                 const float* __restrict__ Wc, const float* __restrict__ Wo) {
    const int j = blockIdx.x;                 // hidden unit 0..4095
    const float* srcs[4] = { Wf + (size_t)j * KX, Wi + (size_t)j * KX,
                             Wc + (size_t)j * KX, Wo + (size_t)j * KX };
#pragma unroll
    for (int gate = 0; gate < 4; gate++) {
        __half* dst = g_wh + (size_t)(j * 4 + gate) * KX;
        const float* row = srcs[gate];
        for (int k4 = threadIdx.x; k4 < KX / 4; k4 += blockDim.x) {
            int k = k4 * 4;
            cvt4_store(*(const float4*)(row + k), &dst[k]);
        }
    }
}

__global__ void convert_wout_kernel(const float* __restrict__ W) {
    const int n = blockIdx.x;
    const float* row = W + (size_t)n * HID;
    __half* dst = g_wouth + (size_t)n * HID;
    for (int k4 = threadIdx.x; k4 < HID / 4; k4 += blockDim.x) {
        int k = k4 * 4;
        cvt4_store(*(const float4*)(row + k), &dst[k]);
    }
}

// ---------------- single-pass fp16 GEMM: C[M,N] = A[M,K] @ W[N,K]^T ----------------
// CTA 64M x 128N, 64 threads = 2 warps (64x64 each over N halves), k-step 64,
// 2-stage cp.async pipeline, 4 CTAs/SM (independent barrier domains).
// PASS 0 (gates): W gate-interleaved; epilogue fuses bias + LSTM activations and
//                 writes it/ht/ct/g_hth directly (no fp32 gates round-trip).
// PASS 1 (logits): plain fp32 store to g_logits.
#define WLD   72                        // smem leading dim (elements); 144 B rows
#define A_EL  (64 * WLD)                // A buffer: 64 rows
#define W_EL  (128 * WLD)               // W buffer: 128 rows
#define STEL  (A_EL + W_EL)             // per stage: 13824 el = 27648 B
#define EPAD  132                       // epilogue smem row stride (floats)

template <int PASS_ID>
__global__ __launch_bounds__(64, 4)
void gemm_mma_kernel(const float* __restrict__ cin,
                     const float* __restrict__ bfp, const float* __restrict__ bip,
                     const float* __restrict__ bcp, const float* __restrict__ bop,
                     float* __restrict__ out_it, float* __restrict__ out_ht,
                     float* __restrict__ out_ct)
{
    constexpr int N = (PASS_ID == 0) ? G4 : OUT_DIM;
    constexpr int K = (PASS_ID == 0) ? KX : HID;
    const __half* __restrict__ A = (PASS_ID == 0) ? g_xh : g_hth;
    const __half* __restrict__ W = (PASS_ID == 0) ? g_wh : g_wouth;

    extern __shared__ __align__(16) __half smem[];   // 2 * STEL elements (reused by epilogue)
    const uint32_t sbase = smem_u32(smem);

    const int tid  = threadIdx.x;
    const int lane = tid & 31;
    const int warp_n = tid >> 5;   // 2 warps over N, 64 cols each

    const int m0 = blockIdx.x * 64;
    const int n0 = blockIdx.y * 128;
    const int niter = K / 64;

    // ---- producer mapping: row = 8 x 16B chunks; thread -> row rP(+8p), chunk cP
    const int rP = tid >> 3, cP = tid & 7;   // rP 0..7
    const __half* baseA = A + (size_t)(m0 + rP) * K + cP * 8;
    const __half* baseW = W + (size_t)(n0 + rP) * K + cP * 8;
    const uint32_t sOffBase = (uint32_t)(rP * WLD + cP * 8) * 2;

    auto issue_stage = [&](int stage, int it) {
        const uint32_t st = sbase + (uint32_t)(stage * STEL) * 2;
        const int k0 = it * 64;
#pragma unroll
        for (int p = 0; p < 8; p++) {    // A: 64 rows
            const uint32_t so = sOffBase + (uint32_t)(p * 8 * WLD) * 2;
            cp16(st + so, baseA + (size_t)(p * 8) * K + k0);
        }
#pragma unroll
        for (int p = 0; p < 16; p++) {   // W: 128 rows
            const uint32_t so = sOffBase + (uint32_t)(p * 8 * WLD) * 2;
            cp16(st + A_EL * 2 + so, baseW + (size_t)(p * 8) * K + k0);
        }
    };

    // ---- consumer ldmatrix lane addressing
    const uint32_t aLane = (uint32_t)(((lane & 7) + ((lane >> 3) & 1) * 8) * WLD
                                      + (lane >> 4) * 8) * 2;
    const uint32_t bLane = (uint32_t)(((warp_n * 64) + (lane & 7) + (lane >> 4) * 8) * WLD
                                      + ((lane >> 3) & 1) * 8) * 2;

    float acc[4][8][4];
#pragma unroll
    for (int mt = 0; mt < 4; mt++)
#pragma unroll
        for (int j = 0; j < 8; j++)
#pragma unroll
            for (int r = 0; r < 4; r++) acc[mt][j][r] = 0.f;

    // prologue: stage 0 in flight
    issue_stage(0, 0); cp_commit();

    int stage = 0;
    for (int it = 0; it < niter; ++it) {
        cp_wait0();        // stage for `it` loaded
        __syncthreads();   // both warps past iter it-1 compute (freed stage^1)

        const uint32_t sA = sbase + (uint32_t)(stage * STEL) * 2;
        const uint32_t sW = sA + A_EL * 2;

#pragma unroll
        for (int kk = 0; kk < 4; ++kk) {
            const uint32_t kb = (uint32_t)(kk * 32);   // 16 elements = 32 bytes

            uint32_t af[4][4], bf[16];
#pragma unroll
            for (int mt = 0; mt < 4; ++mt)
                ldsm4(af[mt], sA + (uint32_t)(mt * 16 * WLD) * 2 + aLane + kb);
#pragma unroll
            for (int np = 0; np < 4; ++np)
                ldsm4(&bf[4 * np], sW + (uint32_t)(np * 16 * WLD) * 2 + bLane + kb);

#pragma unroll
            for (int mt = 0; mt < 4; ++mt)
#pragma unroll
                for (int j = 0; j < 8; ++j)
                    mma16816(acc[mt][j], af[mt], bf[2 * j], bf[2 * j + 1]);

            // issue next stage after kk=0: first LDSM/MMA chain starts immediately
            // post-barrier; loads still covered by kk=1..3 + next-iter head.
            if (kk == 0) {
                if (it + 1 < niter) issue_stage(stage ^ 1, it + 1);
                cp_commit();   // exactly one group per iteration
            }
        }
        stage ^= 1;
    }

    const int erow = lane >> 2;
    const int ecol = (lane & 3) * 2;

    if (PASS_ID == 1) {
        // ---- plain epilogue: fp32 store to g_logits
        float* Cw = g_logits + (size_t)m0 * N + n0 + warp_n * 64;
#pragma unroll
        for (int mt = 0; mt < 4; ++mt)
#pragma unroll
            for (int j = 0; j < 8; ++j) {
                float* p0 = Cw + (size_t)(mt * 16 + erow) * N + j * 8 + ecol;
                *(float2*)p0                   = make_float2(acc[mt][j][0], acc[mt][j][1]);
                *(float2*)(p0 + (size_t)8 * N) = make_float2(acc[mt][j][2], acc[mt][j][3]);
            }
        return;
    }

    // ---- fused LSTM epilogue (PASS 0) ----
    // Stage 64x128 preact tile to smem (fp32, stride EPAD), then each thread
    // handles one batch row: 32 hidden units, float4 = (f,i,c,o) per unit.
    __syncthreads();   // all warps done reading pipeline smem
    float* eps = (float*)smem;
#pragma unroll
    for (int mt = 0; mt < 4; ++mt)
#pragma unroll
        for (int j = 0; j < 8; ++j) {
            float* p0 = eps + (size_t)(mt * 16 + erow) * EPAD + warp_n * 64 + j * 8 + ecol;
            p0[0] = acc[mt][j][0];
            p0[1] = acc[mt][j][1];
            p0[8 * EPAD]     = acc[mt][j][2];
            p0[8 * EPAD + 1] = acc[mt][j][3];
        }
    __syncthreads();

    const int jg0 = n0 >> 2;             // first hidden unit of this tile
    const int brow = m0 + tid;           // this thread's batch row
    const float* epr = eps + (size_t)tid * EPAD;
#pragma unroll 4
    for (int j = 0; j < 32; ++j) {
        float4 g = *(const float4*)(epr + j * 4);   // (f, i, c, o) preacts
        const int jj = jg0 + j;
        float fp = g.x + bfp[jj];
        float ip = g.y + bip[jj];
        float cp = g.z + bcp[jj];
        float op = g.w + bop[jj];
        float ft = 1.f / (1.f + __expf(-fp));
        float it = 1.f / (1.f + __expf(-ip));
        float cb = tanhf(cp);
        float ct = ft * cin[(size_t)brow * HID + jj] + it * cb;
        float ot = 1.f / (1.f + __expf(-op));
        float ht = ot * tanhf(ct);
        out_it[(size_t)brow * HID + jj] = it;
        out_ht[(size_t)brow * HID + jj] = ht;
        out_ct[(size_t)brow * HID + jj] = ct;
        g_hth[(size_t)brow * HID + jj] = __float2half(ht);
    }
}

// ---------------- log_softmax ----------------
__global__ void logsoftmax_kernel(const float* __restrict__ bout,
                                  float* __restrict__ out)
{
    const int row = blockIdx.x;
    const float* x = g_logits + (size_t)row * OUT_DIM;
    float* y = out + (size_t)row * OUT_DIM;
    __shared__ float red[256];
    const int tid = threadIdx.x;

    float mx = -INFINITY;
    for (int j = tid; j < OUT_DIM; j += 256) mx = fmaxf(mx, x[j] + bout[j]);
    red[tid] = mx; __syncthreads();
    for (int s = 128; s > 0; s >>= 1) {
        if (tid < s) red[tid] = fmaxf(red[tid], red[tid + s]);
        __syncthreads();
    }
    mx = red[0];
    __syncthreads();

    float sum = 0.f;
    for (int j = tid; j < OUT_DIM; j += 256) sum += __expf(x[j] + bout[j] - mx);
    red[tid] = sum; __syncthreads();
    for (int s = 128; s > 0; s >>= 1) {
        if (tid < s) red[tid] += red[tid + s];
        __syncthreads();
    }
    float lse = mx + logf(red[0]);

    for (int j = tid; j < OUT_DIM; j += 256) y[j] = x[j] + bout[j] - lse;
}

// ---------------- launch ----------------
extern "C" void kernel_launch(void* const* d_in, const int* in_sizes, int n_in,
                              void* d_out, int out_size)
{
    const float* in_i  = (const float*)d_in[0];
    const float* in_h  = (const float*)d_in[1];
    const float* in_c  = (const float*)d_in[2];
    const float* Wf    = (const float*)d_in[3];
    const float* bf_   = (const float*)d_in[4];
    const float* Wi    = (const float*)d_in[5];
    const float* bi_   = (const float*)d_in[6];
    const float* Wc    = (const float*)d_in[7];
    const float* bc_   = (const float*)d_in[8];
    const float* Wo    = (const float*)d_in[9];
    const float* bo_   = (const float*)d_in[10];
    const float* Wout  = (const float*)d_in[11];
    const float* bout  = (const float*)d_in[12];

    float* out    = (float*)d_out;
    float* out_it = out;
    float* out_ht = out + (size_t)BATCH * HID;
    float* out_ct = out + 2 * (size_t)BATCH * HID;
    float* out_ls = out + 3 * (size_t)BATCH * HID;

    const int SMEM_DYN = 2 * STEL * 2;   // 55296 B (epilogue's 64*132*4=33792 fits inside)
    cudaFuncSetAttribute(gemm_mma_kernel<0>,
                         cudaFuncAttributeMaxDynamicSharedMemorySize, SMEM_DYN);
    cudaFuncSetAttribute(gemm_mma_kernel<1>,
                         cudaFuncAttributeMaxDynamicSharedMemorySize, SMEM_DYN);

    // 1) fp32 -> fp16 conversions
    convert_x_kernel<<<BATCH, 256>>>(in_i, in_h);
    convert_w_kernel<<<HID, 256>>>(Wf, Wi, Wc, Wo);     // gate-interleaved rows
    convert_wout_kernel<<<OUT_DIM, 256>>>(Wout);

    // 2) gates GEMM + fused bias/LSTM epilogue -> it, ht, ct, g_hth
    {
        dim3 grid(BATCH / 64, G4 / 128);
        gemm_mma_kernel<0><<<grid, 64, SMEM_DYN>>>(in_c, bf_, bi_, bc_, bo_,
                                                   out_it, out_ht, out_ct);
    }

    // 3) logits = ht @ Wout^T
    {
        dim3 grid(BATCH / 64, OUT_DIM / 128);
        gemm_mma_kernel<1><<<grid, 64, SMEM_DYN>>>(nullptr, nullptr, nullptr,
                                                   nullptr, nullptr,
                                                   nullptr, nullptr, nullptr);
    }

    // 4) log_softmax(logits + bout) -> out
    logsoftmax_kernel<<<BATCH, 256>>>(bout, out_ls);
}